// round 14
// baseline (speedup 1.0000x reference)
#include <cuda_runtime.h>
#include <cstdint>

// out[b,t,:] = [ features[b,t,:] @ W^T + bias , pe(positions[t]) ]
// B=16384, T=64, F=16, Dh=128.
//
// Round-13 winner (direct STG from registers, warp-private pipelines, zero
// loop barriers) + st.global.cs evict-first hints on the output stream and
// pe store hoisted ahead of the FMA chain.

#define T_DIM 64
#define F_DIM 16
#define DH    128
#define GRID  296
#define TPB   256
#define WPB   8
#define WTOT  (GRID * WPB)       // 2368, multiple of 16

__device__ __forceinline__ uint32_t smem_u32(const void* p)
{
    return (uint32_t)__cvta_generic_to_shared(p);
}
__device__ __forceinline__ void cp16(uint32_t dst, const void* src)
{
    asm volatile("cp.async.cg.shared.global [%0], [%1], 16;" :: "r"(dst), "l"(src));
}
__device__ __forceinline__ unsigned long long pack2(float a, float b)
{
    unsigned long long r;
    asm("mov.b64 %0, {%1, %2};" : "=l"(r) : "f"(a), "f"(b));
    return r;
}
__device__ __forceinline__ void fma2(unsigned long long& d,
                                     unsigned long long a, unsigned long long b)
{
    asm("fma.rn.f32x2 %0, %1, %2, %0;" : "+l"(d) : "l"(a), "l"(b));
}

__global__ __launch_bounds__(TPB, 2) void obs_embed_kernel(
    const float* __restrict__ features,   // [B,64,16]
    const float* __restrict__ W,          // [128,16]
    const float* __restrict__ bias,       // [128]
    const int*   __restrict__ positions,  // [64]
    float*       __restrict__ out,        // [B,64,256]
    int nUnits)                           // B*16 (unit = 4 rows)
{
    // Warp-private feature staging: [warp][buf][4 rows * 16 floats].
    __shared__ float ffb[WPB][2][64];

    const int lane = threadIdx.x & 31;
    const int warp = threadIdx.x >> 5;
    const int gw   = blockIdx.x * WPB + warp;
    const int t0   = (gw & 15) * 4;      // fixed t-block for this warp

    int u = gw;

    // Prologue: prefetch features for iters 0 and 1 (256B each; 16 lanes).
    #pragma unroll
    for (int i = 0; i < 2; ++i) {
        int up = u + i * WTOT;
        if (up < nUnits && lane < 16)
            cp16(smem_u32(&ffb[warp][i][lane * 4]),
                 features + (size_t)up * 64 + lane * 4);
        asm volatile("cp.async.commit_group;");
    }

    // pe in REGISTERS: 4 fixed t's, lane's 4 cols (pairs 2*lane, 2*lane+1).
    float4 pe[4];
    {
        const float c0 = -13.287712379549449f / 32.0f;
        const float if0 = exp2f((float)(2 * lane)     * c0);
        const float if1 = exp2f((float)(2 * lane + 1) * c0);
        #pragma unroll
        for (int r = 0; r < 4; ++r) {
            float pos = (float)__ldg(positions + t0 + r);
            float s0, cc0, s1, cc1;
            sincosf(pos * if0, &s0, &cc0);
            sincosf(pos * if1, &s1, &cc1);
            pe[r] = make_float4(s0, cc0, s1, cc1);
        }
    }

    // W into packed registers. Lane owns output cols d = 4*lane + {0..3}.
    unsigned long long wp0[16], wp1[16];
    {
        const float4* Wv = reinterpret_cast<const float4*>(W);
        #pragma unroll
        for (int q = 0; q < 4; ++q) {
            float4 w0 = __ldg(Wv + (4 * lane + 0) * 4 + q);
            float4 w1 = __ldg(Wv + (4 * lane + 1) * 4 + q);
            float4 w2 = __ldg(Wv + (4 * lane + 2) * 4 + q);
            float4 w3 = __ldg(Wv + (4 * lane + 3) * 4 + q);
            wp0[4*q+0] = pack2(w0.x, w1.x);  wp1[4*q+0] = pack2(w2.x, w3.x);
            wp0[4*q+1] = pack2(w0.y, w1.y);  wp1[4*q+1] = pack2(w2.y, w3.y);
            wp0[4*q+2] = pack2(w0.z, w1.z);  wp1[4*q+2] = pack2(w2.z, w3.z);
            wp0[4*q+3] = pack2(w0.w, w1.w);  wp1[4*q+3] = pack2(w2.w, w3.w);
        }
    }
    const unsigned long long bp0 = pack2(__ldg(bias + 4 * lane + 0),
                                         __ldg(bias + 4 * lane + 1));
    const unsigned long long bp1 = pack2(__ldg(bias + 4 * lane + 2),
                                         __ldg(bias + 4 * lane + 3));

    int p = 0;
    for (; u < nUnits; u += WTOT, p ^= 1) {
        // Features for u (committed 2 iters ago) ready; <=1 group may remain.
        asm volatile("cp.async.wait_group 1;");
        __syncwarp();   // cross-lane visibility of the 16 lanes' copies

        const float* fcur = &ffb[warp][p][0];

        #pragma unroll
        for (int rr = 0; rr < 4; ++rr) {
            float* orow = out + ((size_t)u * 4 + rr) * 256;

            // pe half first: independent of the FMA chain, issues early
            // under the fma latency. Evict-first streaming store.
            asm volatile("st.global.cs.v4.f32 [%0], {%1, %2, %3, %4};"
                         :: "l"(orow + DH + lane * 4),
                            "f"(pe[rr].x), "f"(pe[rr].y),
                            "f"(pe[rr].z), "f"(pe[rr].w) : "memory");

            const float4* frow = reinterpret_cast<const float4*>(fcur + rr * 16);
            unsigned long long a0 = bp0, a1 = bp1;
            #pragma unroll
            for (int q = 0; q < 4; ++q) {
                const float4 f = frow[q];   // broadcast LDS, conflict-free
                unsigned long long ff;
                ff = pack2(f.x, f.x); fma2(a0, ff, wp0[4*q+0]); fma2(a1, ff, wp1[4*q+0]);
                ff = pack2(f.y, f.y); fma2(a0, ff, wp0[4*q+1]); fma2(a1, ff, wp1[4*q+1]);
                ff = pack2(f.z, f.z); fma2(a0, ff, wp0[4*q+2]); fma2(a1, ff, wp1[4*q+2]);
                ff = pack2(f.w, f.w); fma2(a0, ff, wp0[4*q+3]); fma2(a1, ff, wp1[4*q+3]);
            }
            asm volatile("st.global.cs.v2.u64 [%0], {%1, %2};"
                         :: "l"(orow + lane * 4), "l"(a0), "l"(a1) : "memory");
        }

        // Prefetch u + 2*WTOT into buffer p (reads above complete in-order).
        {
            int un = u + 2 * WTOT;
            if (un < nUnits && lane < 16)
                cp16(smem_u32(&ffb[warp][p][lane * 4]),
                     features + (size_t)un * 64 + lane * 4);
            asm volatile("cp.async.commit_group;");
        }
    }
    asm volatile("cp.async.wait_group 0;");
}

extern "C" void kernel_launch(void* const* d_in, const int* in_sizes, int n_in,
                              void* d_out, int out_size)
{
    const float* features  = (const float*)d_in[0];
    const float* W         = (const float*)d_in[1];
    const float* bias      = (const float*)d_in[2];
    const int*   positions = (const int*)d_in[3];
    float* out = (float*)d_out;

    const int B = in_sizes[0] / (T_DIM * F_DIM);

    obs_embed_kernel<<<GRID, TPB>>>(features, W, bias, positions, out, B * 16);
}